// round 8
// baseline (speedup 1.0000x reference)
#include <cuda_runtime.h>
#include <cstdint>

#define N_PTS   16384
#define B_SZ    8
#define NPT     512
#define KNB     32
#define NCH     128
#define R2      0.04f

#define CLUSTER 8
#define PTS_PER_CTA (N_PTS / CLUSTER)   // 2048
#define FPS_THR 512
#define PPT (PTS_PER_CTA / FPS_THR)     // 4 points per thread

// ---------------- device scratch (no runtime allocation allowed) ----------------
__device__ float g_n2   [B_SZ * N_PTS];               // per-point squared norms
__device__ int   g_idx  [B_SZ * NPT * KNB];           // ball-query neighbor lists
__device__ float g_featT[(size_t)B_SZ * N_PTS * NCH]; // features transposed to (B,N,C)

// ---------------- packed f32x2 helpers (two independent IEEE-rn ops) ------------
__device__ __forceinline__ unsigned long long f2_add(unsigned long long a, unsigned long long b) {
    unsigned long long r; asm("add.rn.f32x2 %0, %1, %2;" : "=l"(r) : "l"(a), "l"(b)); return r;
}
__device__ __forceinline__ unsigned long long f2_mul(unsigned long long a, unsigned long long b) {
    unsigned long long r; asm("mul.rn.f32x2 %0, %1, %2;" : "=l"(r) : "l"(a), "l"(b)); return r;
}
__device__ __forceinline__ unsigned long long f2_pack(float lo, float hi) {
    unsigned long long r; asm("mov.b64 %0, {%1, %2};" : "=l"(r) : "f"(lo), "f"(hi)); return r;
}
__device__ __forceinline__ void f2_unpack(float& lo, float& hi, unsigned long long v) {
    asm("mov.b64 {%0, %1}, %2;" : "=f"(lo), "=f"(hi) : "l"(v));
}
__device__ __forceinline__ uint32_t smem_u32(const void* p) {
    uint32_t a;
    asm("{ .reg .u64 t; cvta.to.shared.u64 t, %1; cvt.u32.u64 %0, t; }" : "=r"(a) : "l"(p));
    return a;
}
// acquire-cluster parity wait on a LOCAL mbarrier (HW sleep, not the 490-cyc cluster bar)
__device__ __forceinline__ void mbar_wait_cluster(uint32_t mbar, uint32_t parity) {
    uint32_t done;
    asm volatile(
        "{\n\t.reg .pred p;\n\t"
        "mbarrier.try_wait.parity.acquire.cluster.shared::cta.b64 p, [%1], %2;\n\t"
        "selp.b32 %0, 1, 0, p;\n\t}"
        : "=r"(done) : "r"(mbar), "r"(parity) : "memory");
    if (!done) {
        asm volatile(
            "{\n\t.reg .pred P1;\n\t"
            "WL_%=:\n\t"
            "mbarrier.try_wait.parity.acquire.cluster.shared::cta.b64 P1, [%0], %1, 0x989680;\n\t"
            "@P1 bra.uni WD_%=;\n\t"
            "bra.uni WL_%=;\n\t"
            "WD_%=:\n\t}"
            :: "r"(mbar), "r"(parity) : "memory");
    }
}

// =================================================================================
// Kernel 1: FPS — cluster of 8 CTAs per batch (64 CTAs total), 512 thr/CTA,
// 4 points/thread entirely in registers (f32x2-packed). Per iteration:
//   1. exact min-update (d = ((dx*dx+dy*dy)+dz*dz), plain rn ops, no FMA)
//   2. warp argmax via REDUX (tie -> min global index), winner stages coords
//   3. __syncthreads; warp0 selects CTA winner; lanes 0..7 store the entry into
//      every peer's mailbox (st.shared::cluster) then mbarrier.arrive.release
//      on the peer's full[it&1]
//   4. all threads acquire-wait the LOCAL mbarrier (wakeup ~60-90 cyc, no L1
//      flush) and reduce the 8 mailbox entries -> next centroid in registers.
// Slot reuse (2 slots) is safe: writes of slot s at it+2 are ordered after all
// CTAs' reads of slot s at it through the it+1 arrivals.
// =================================================================================
__global__ void __launch_bounds__(FPS_THR, 1) __cluster_dims__(CLUSTER, 1, 1)
fps_kernel(const float* __restrict__ xyz, float* __restrict__ out_newxyz)
{
    const int rank = blockIdx.x;          // CTA rank within cluster (0..7)
    const int b    = blockIdx.y;          // batch
    const int t    = threadIdx.x;
    const int lane = t & 31;
    const int wid  = t >> 5;              // 0..15

    const float* X = xyz + (size_t)b * N_PTS * 3;

    __shared__ unsigned s_wv[16];
    __shared__ int      s_wi[16];
    __shared__ float    s_cand[16][3];
    __shared__ unsigned mbox[2][CLUSTER][6];           // bits, idx, x, y, z, pad
    __shared__ alignas(8) unsigned long long s_full[2]; // mbarriers (count = 8)

    const int base = rank * PTS_PER_CTA + t * PPT;   // first owned global point

    if (t == 0) {
        const uint32_t m0 = smem_u32(&s_full[0]);
        const uint32_t m1 = smem_u32(&s_full[1]);
        asm volatile("mbarrier.init.shared.b64 [%0], %1;" :: "r"(m0), "r"(CLUSTER) : "memory");
        asm volatile("mbarrier.init.shared.b64 [%0], %1;" :: "r"(m1), "r"(CLUSTER) : "memory");
    }

    // ---- load 4 points (12 floats = 3x float4, 16B-aligned) ----
    const float4 q0 = *(const float4*)(X + (size_t)base * 3);
    const float4 q1 = *(const float4*)(X + (size_t)base * 3 + 4);
    const float4 q2 = *(const float4*)(X + (size_t)base * 3 + 8);
    const float ax0 = q0.x, ay0 = q0.y, az0 = q0.z;
    const float ax1 = q0.w, ay1 = q1.x, az1 = q1.y;
    const float ax2 = q1.z, ay2 = q1.w, az2 = q2.x;
    const float ax3 = q2.y, ay3 = q2.z, az3 = q2.w;

    // squared norms for the ball-query kernel (exact square-then-sum)
    {
        float4 n;
        n.x = __fadd_rn(__fadd_rn(__fmul_rn(ax0,ax0), __fmul_rn(ay0,ay0)), __fmul_rn(az0,az0));
        n.y = __fadd_rn(__fadd_rn(__fmul_rn(ax1,ax1), __fmul_rn(ay1,ay1)), __fmul_rn(az1,az1));
        n.z = __fadd_rn(__fadd_rn(__fmul_rn(ax2,ax2), __fmul_rn(ay2,ay2)), __fmul_rn(az2,az2));
        n.w = __fadd_rn(__fadd_rn(__fmul_rn(ax3,ax3), __fmul_rn(ay3,ay3)), __fmul_rn(az3,az3));
        *(float4*)(g_n2 + (size_t)b * N_PTS + base) = n;
    }

    unsigned long long xq[2], yq[2], zq[2];
    xq[0] = f2_pack(ax0, ax1); xq[1] = f2_pack(ax2, ax3);
    yq[0] = f2_pack(ay0, ay1); yq[1] = f2_pack(ay2, ay3);
    zq[0] = f2_pack(az0, az1); zq[1] = f2_pack(az2, az3);
    float pd[4] = {1e10f, 1e10f, 1e10f, 1e10f};

    float cx = __ldg(X + 0), cy = __ldg(X + 1), cz = __ldg(X + 2);
    if (rank == 0 && t == 0) {
        float* o = out_newxyz + (size_t)b * NPT * 3;
        o[0] = cx; o[1] = cy; o[2] = cz;
    }

    // all mbarrier inits visible cluster-wide before any remote arrive
    __syncthreads();
    asm volatile("barrier.cluster.arrive.aligned;" ::: "memory");
    asm volatile("barrier.cluster.wait.aligned;"   ::: "memory");

    for (int it = 0; it < NPT - 1; ++it) {
        const int      slot  = it & 1;
        const unsigned phase = (unsigned)((it >> 1) & 1);

        const unsigned long long ncx = f2_pack(-cx, -cx);
        const unsigned long long ncy = f2_pack(-cy, -cy);
        const unsigned long long ncz = f2_pack(-cz, -cz);

        #pragma unroll
        for (int k = 0; k < 2; k++) {
            const unsigned long long dx = f2_add(xq[k], ncx);
            const unsigned long long dy = f2_add(yq[k], ncy);
            const unsigned long long dz = f2_add(zq[k], ncz);
            const unsigned long long s  =
                f2_add(f2_add(f2_mul(dx, dx), f2_mul(dy, dy)), f2_mul(dz, dz));
            float d0, d1;
            f2_unpack(d0, d1, s);
            pd[2*k]   = fminf(pd[2*k],   d0);
            pd[2*k+1] = fminf(pd[2*k+1], d1);
        }
        const float bestv = fmaxf(fmaxf(pd[0], pd[1]), fmaxf(pd[2], pd[3]));
        const unsigned bb = __float_as_uint(bestv);   // dists >= +0: u32 order == float order

        const unsigned wmax = __reduce_max_sync(0xffffffffu, bb);
        int tidx = 0x7fffffff;
        if (bb == wmax) {
            const float gm = __uint_as_float(wmax);
            #pragma unroll
            for (int j = PPT - 1; j >= 0; --j)
                if (pd[j] == gm) tidx = base + j;     // reverse scan -> first index
        }
        const unsigned wmin = __reduce_min_sync(0xffffffffu, (unsigned)tidx);
        if (bb == wmax && tidx == (int)wmin) {         // exactly one thread per warp
            #pragma unroll
            for (int j = 0; j < PPT; j++) {
                if (tidx == base + j) {
                    float lo, hi;
                    f2_unpack(lo, hi, xq[j >> 1]); s_cand[wid][0] = (j & 1) ? hi : lo;
                    f2_unpack(lo, hi, yq[j >> 1]); s_cand[wid][1] = (j & 1) ? hi : lo;
                    f2_unpack(lo, hi, zq[j >> 1]); s_cand[wid][2] = (j & 1) ? hi : lo;
                }
            }
        }
        if (lane == 0) { s_wv[wid] = wmax; s_wi[wid] = (int)wmin; }
        __syncthreads();

        if (wid == 0) {
            const unsigned bits = (lane < 16) ? s_wv[lane] : 0u;
            const unsigned idx  = (lane < 16) ? (unsigned)s_wi[lane] : 0xffffffffu;
            const unsigned m    = __reduce_max_sync(0xffffffffu, bits);
            const unsigned cidx = __reduce_min_sync(0xffffffffu, (bits == m) ? idx : 0xffffffffu);
            const unsigned wl   = __reduce_min_sync(0xffffffffu,
                                    (bits == m && idx == cidx) ? (unsigned)lane : 32u);
            const float wx = s_cand[wl][0];
            const float wy = s_cand[wl][1];
            const float wz = s_cand[wl][2];

            if (lane < CLUSTER) {
                const uint32_t loc  = smem_u32(&mbox[slot][rank][0]);
                const uint32_t locb = smem_u32(&s_full[slot]);
                uint32_t rem, remb;
                asm("mapa.shared::cluster.u32 %0, %1, %2;" : "=r"(rem)  : "r"(loc),  "r"(lane));
                asm("mapa.shared::cluster.u32 %0, %1, %2;" : "=r"(remb) : "r"(locb), "r"(lane));
                unsigned long long a = ((unsigned long long)cidx << 32) | m;
                unsigned long long c = ((unsigned long long)__float_as_uint(wy) << 32)
                                      | __float_as_uint(wx);
                asm volatile("st.shared::cluster.b64 [%0], %1;"    :: "r"(rem), "l"(a) : "memory");
                asm volatile("st.shared::cluster.b64 [%0+8], %1;"  :: "r"(rem), "l"(c) : "memory");
                asm volatile("st.shared::cluster.b32 [%0+16], %1;" :: "r"(rem),
                             "r"(__float_as_uint(wz)) : "memory");
                // release orders the mailbox stores before this arrival is observed
                asm volatile("mbarrier.arrive.release.cluster.shared::cluster.b64 _, [%0];"
                             :: "r"(remb) : "memory");
            }
        }

        // wait on LOCAL barrier for all 8 arrivals of this slot/phase
        mbar_wait_cluster(smem_u32(&s_full[slot]), phase);

        // every thread reduces the 8 mailbox entries (LDS broadcasts)
        unsigned bbits = 0u, bidx = 0xffffffffu, bx = 0, by = 0, bz = 0;
        #pragma unroll
        for (int r = 0; r < CLUSTER; r++) {
            const unsigned mb = mbox[slot][r][0];
            const unsigned mi = mbox[slot][r][1];
            const bool take = (mb > bbits) || (mb == bbits && mi < bidx);
            if (take) {
                bbits = mb; bidx = mi;
                bx = mbox[slot][r][2];
                by = mbox[slot][r][3];
                bz = mbox[slot][r][4];
            }
        }
        cx = __uint_as_float(bx);
        cy = __uint_as_float(by);
        cz = __uint_as_float(bz);

        if (rank == 0 && t == 0) {
            float* o = out_newxyz + ((size_t)b * NPT + it + 1) * 3;
            o[0] = cx; o[1] = cy; o[2] = cz;
        }
    }

    // keep the cluster alive until all CTAs consumed their final mailboxes
    asm volatile("barrier.cluster.arrive.aligned;" ::: "memory");
    asm volatile("barrier.cluster.wait.aligned;"   ::: "memory");
}

// =================================================================================
// Kernel 2: feature transpose (B,C,N) -> (B,N,C), tiled 32x32 through smem.
// =================================================================================
__global__ void __launch_bounds__(256)
transpose_kernel(const float* __restrict__ feat)
{
    __shared__ float tile[32][33];
    const int b  = blockIdx.z;
    const int n0 = blockIdx.x * 32;
    const int c0 = blockIdx.y * 32;
    const int tx = threadIdx.x, ty = threadIdx.y;

    const float* src = feat + (size_t)b * NCH * N_PTS;
    #pragma unroll
    for (int i = 0; i < 32; i += 8)
        tile[ty + i][tx] = src[(size_t)(c0 + ty + i) * N_PTS + n0 + tx];
    __syncthreads();

    float* dst = g_featT + (size_t)b * N_PTS * NCH;
    #pragma unroll
    for (int i = 0; i < 32; i += 8)
        dst[(size_t)(n0 + ty + i) * NCH + c0 + tx] = tile[tx][ty + i];
}

// =================================================================================
// Kernel 3: ball query — one warp per centroid, early exit after K found.
// Distance matches the reference's expanded form: d = ((-2*dot) + s2) + n2.
// Qualify iff !(d > r^2); first K in index order; pad with first.
// =================================================================================
__global__ void __launch_bounds__(256)
ball_kernel(const float* __restrict__ xyz, const float* __restrict__ newxyz)
{
    const int wig    = (blockIdx.x * 256 + threadIdx.x) >> 5;   // b*512 + s
    const int lane   = threadIdx.x & 31;
    const int wlocal = threadIdx.x >> 5;
    __shared__ int sid[8][KNB];

    const int b = wig >> 9;
    const float* C = newxyz + (size_t)wig * 3;
    const float cx = C[0], cy = C[1], cz = C[2];
    const float s2 = __fadd_rn(__fadd_rn(__fmul_rn(cx,cx), __fmul_rn(cy,cy)), __fmul_rn(cz,cz));

    const float* X  = xyz  + (size_t)b * N_PTS * 3;
    const float* NN = g_n2 + (size_t)b * N_PTS;

    int cnt = 0;
    for (int basep = 0; basep < N_PTS && cnt < KNB; basep += 32) {
        const int p = basep + lane;
        const float x = X[3*p], y = X[3*p+1], z = X[3*p+2];
        float dot = __fmul_rn(cx, x);
        dot = __fmaf_rn(cy, y, dot);
        dot = __fmaf_rn(cz, z, dot);
        const float d = __fadd_rn(__fadd_rn(__fmul_rn(-2.0f, dot), s2), NN[p]);
        const bool q = !(d > R2);
        const unsigned m = __ballot_sync(0xffffffffu, q);
        const int pos = cnt + __popc(m & ((1u << lane) - 1u));
        if (q && pos < KNB) sid[wlocal][pos] = p;
        cnt += __popc(m);
    }
    __syncwarp();

    const int first = sid[wlocal][0];          // cnt==0 impossible: centroid itself qualifies
    const int v = (lane < cnt) ? sid[wlocal][lane] : first;
    g_idx[(size_t)wig * KNB + lane] = v;
}

// =================================================================================
// Kernel 4: masked max pool from transposed features — block per (b,s), thread=c.
// Warp lanes read consecutive channels -> fully coalesced 128B gathers.
// =================================================================================
__global__ void __launch_bounds__(128)
pool_kernel(float* __restrict__ out)
{
    const int g = blockIdx.x;             // b*512 + s
    const int c = threadIdx.x;
    const int b = g >> 9;
    const int s = g & 511;

    __shared__ int nb[KNB];
    if (c < KNB) nb[c] = g_idx[(size_t)g * KNB + c];
    __syncthreads();

    const float* F = g_featT + (size_t)b * N_PTS * NCH;

    float m0 = F[(size_t)nb[0] * NCH + c];
    float m1 = F[(size_t)nb[1] * NCH + c];
    float m2 = F[(size_t)nb[2] * NCH + c];
    float m3 = F[(size_t)nb[3] * NCH + c];
    #pragma unroll
    for (int k = 4; k < KNB; k += 4) {
        m0 = fmaxf(m0, F[(size_t)nb[k]   * NCH + c]);
        m1 = fmaxf(m1, F[(size_t)nb[k+1] * NCH + c]);
        m2 = fmaxf(m2, F[(size_t)nb[k+2] * NCH + c]);
        m3 = fmaxf(m3, F[(size_t)nb[k+3] * NCH + c]);
    }
    const float m = fmaxf(fmaxf(m0, m1), fmaxf(m2, m3));

    out[(size_t)B_SZ*NPT*3 + ((size_t)b * NCH + c) * NPT + s] = m;
}

// =================================================================================
extern "C" void kernel_launch(void* const* d_in, const int* in_sizes, int n_in,
                              void* d_out, int out_size)
{
    const float* xyz  = (const float*)d_in[0];   // (8, 16384, 3) fp32
    const float* feat = (const float*)d_in[1];   // (8, 128, 16384) fp32
    float* out = (float*)d_out;                  // new_xyz (12288) ++ sub_features (524288)

    dim3 tgrid(N_PTS / 32, NCH / 32, B_SZ);
    dim3 tblk(32, 8);
    transpose_kernel<<<tgrid, tblk>>>(feat);

    dim3 fgrid(CLUSTER, B_SZ);
    fps_kernel<<<fgrid, FPS_THR>>>(xyz, out);

    ball_kernel<<<(B_SZ * NPT * 32) / 256, 256>>>(xyz, out);
    pool_kernel<<<B_SZ * NPT, 128>>>(out);
}

// round 11
// speedup vs baseline: 1.0963x; 1.0963x over previous
#include <cuda_runtime.h>
#include <cstdint>

#define N_PTS   16384
#define B_SZ    8
#define NPT     512
#define KNB     32
#define NCH     128
#define R2      0.04f

#define CLUSTER 8
#define PTS_PER_CTA (N_PTS / CLUSTER)   // 2048
#define FPS_THR 512
#define PPT (PTS_PER_CTA / FPS_THR)     // 4 points per thread

// ---------------- device scratch (no runtime allocation allowed) ----------------
__device__ float g_n2   [B_SZ * N_PTS];               // per-point squared norms
__device__ int   g_idx  [B_SZ * NPT * KNB];           // ball-query neighbor lists
__device__ float g_featT[(size_t)B_SZ * N_PTS * NCH]; // features transposed to (B,N,C)

// ---------------- packed f32x2 helpers (two independent IEEE-rn ops) ------------
__device__ __forceinline__ unsigned long long f2_add(unsigned long long a, unsigned long long b) {
    unsigned long long r; asm("add.rn.f32x2 %0, %1, %2;" : "=l"(r) : "l"(a), "l"(b)); return r;
}
__device__ __forceinline__ unsigned long long f2_mul(unsigned long long a, unsigned long long b) {
    unsigned long long r; asm("mul.rn.f32x2 %0, %1, %2;" : "=l"(r) : "l"(a), "l"(b)); return r;
}
__device__ __forceinline__ unsigned long long f2_pack(float lo, float hi) {
    unsigned long long r; asm("mov.b64 %0, {%1, %2};" : "=l"(r) : "f"(lo), "f"(hi)); return r;
}
__device__ __forceinline__ void f2_unpack(float& lo, float& hi, unsigned long long v) {
    asm("mov.b64 {%0, %1}, %2;" : "=f"(lo), "=f"(hi) : "l"(v));
}
__device__ __forceinline__ uint32_t smem_u32(const void* p) {
    uint32_t a;
    asm("{ .reg .u64 t; cvta.to.shared.u64 t, %1; cvt.u32.u64 %0, t; }" : "=r"(a) : "l"(p));
    return a;
}

// =================================================================================
// Kernel 1: FPS — cluster of 8 CTAs per batch (64 CTAs total), 512 thr/CTA,
// 4 points/thread entirely in registers (f32x2-packed). Per iteration:
//   1. exact min-update (d = ((dx*dx+dy*dy)+dz*dz), plain rn ops, no FMA)
//   2. warp argmax: ONE REDUX.max + ballot + ffs (lane order == index order, so
//      lowest tied lane == first occurrence); the single winner lane writes
//      (bits, idx, x, y, z) straight from registers to smem
//   3. __syncthreads; warp0: ONE REDUX.max + ballot + ffs over the 16 warp
//      entries (warp order == index-block order); lanes 0..7 push the CTA
//      winner into every peer's mailbox (mapa hoisted out of the loop)
//   4. ONE barrier.cluster (proven R6 protocol); every thread reduces the 8
//      mailbox entries -> next centroid in registers.
// Tie-break at every level = lowest lane/warp/rank = smallest global index ==
// jnp.argmax first-occurrence semantics. Arithmetic identical to R6 (rel_err 0).
// =================================================================================
__global__ void __launch_bounds__(FPS_THR, 1) __cluster_dims__(CLUSTER, 1, 1)
fps_kernel(const float* __restrict__ xyz, float* __restrict__ out_newxyz)
{
    const int rank = blockIdx.x;          // CTA rank within cluster (0..7)
    const int b    = blockIdx.y;          // batch
    const int t    = threadIdx.x;
    const int lane = t & 31;
    const int wid  = t >> 5;              // 0..15

    const float* X = xyz + (size_t)b * N_PTS * 3;

    __shared__ unsigned s_wv[16];
    __shared__ int      s_wi[16];
    __shared__ float    s_cand[16][3];
    __shared__ unsigned mbox[2][CLUSTER][6];   // bits, idx, x, y, z, pad (24B stride)

    const int base = rank * PTS_PER_CTA + t * PPT;   // first owned global point

    // ---- load 4 points (12 floats = 3x float4, 48B-aligned) ----
    const float4 q0 = *(const float4*)(X + (size_t)base * 3);
    const float4 q1 = *(const float4*)(X + (size_t)base * 3 + 4);
    const float4 q2 = *(const float4*)(X + (size_t)base * 3 + 8);
    const float ax0 = q0.x, ay0 = q0.y, az0 = q0.z;
    const float ax1 = q0.w, ay1 = q1.x, az1 = q1.y;
    const float ax2 = q1.z, ay2 = q1.w, az2 = q2.x;
    const float ax3 = q2.y, ay3 = q2.z, az3 = q2.w;

    // squared norms for the ball-query kernel (exact square-then-sum)
    {
        float4 n;
        n.x = __fadd_rn(__fadd_rn(__fmul_rn(ax0,ax0), __fmul_rn(ay0,ay0)), __fmul_rn(az0,az0));
        n.y = __fadd_rn(__fadd_rn(__fmul_rn(ax1,ax1), __fmul_rn(ay1,ay1)), __fmul_rn(az1,az1));
        n.z = __fadd_rn(__fadd_rn(__fmul_rn(ax2,ax2), __fmul_rn(ay2,ay2)), __fmul_rn(az2,az2));
        n.w = __fadd_rn(__fadd_rn(__fmul_rn(ax3,ax3), __fmul_rn(ay3,ay3)), __fmul_rn(az3,az3));
        *(float4*)(g_n2 + (size_t)b * N_PTS + base) = n;
    }

    unsigned long long xq[2], yq[2], zq[2];
    xq[0] = f2_pack(ax0, ax1); xq[1] = f2_pack(ax2, ax3);
    yq[0] = f2_pack(ay0, ay1); yq[1] = f2_pack(ay2, ay3);
    zq[0] = f2_pack(az0, az1); zq[1] = f2_pack(az2, az3);
    float pd[4] = {1e10f, 1e10f, 1e10f, 1e10f};

    // hoisted remote mailbox addresses (warp0 lanes 0..7 are the pushers)
    uint32_t remA0 = 0, remA1 = 0;
    if (wid == 0 && lane < CLUSTER) {
        const uint32_t l0 = smem_u32(&mbox[0][rank][0]);
        const uint32_t l1 = smem_u32(&mbox[1][rank][0]);
        asm("mapa.shared::cluster.u32 %0, %1, %2;" : "=r"(remA0) : "r"(l0), "r"(lane));
        asm("mapa.shared::cluster.u32 %0, %1, %2;" : "=r"(remA1) : "r"(l1), "r"(lane));
    }

    float cx = __ldg(X + 0), cy = __ldg(X + 1), cz = __ldg(X + 2);
    if (rank == 0 && t == 0) {
        float* o = out_newxyz + (size_t)b * NPT * 3;
        o[0] = cx; o[1] = cy; o[2] = cz;
    }

    for (int it = 0; it < NPT - 1; ++it) {
        const int slot = it & 1;

        const unsigned long long ncx = f2_pack(-cx, -cx);
        const unsigned long long ncy = f2_pack(-cy, -cy);
        const unsigned long long ncz = f2_pack(-cz, -cz);

        #pragma unroll
        for (int k = 0; k < 2; k++) {
            const unsigned long long dx = f2_add(xq[k], ncx);
            const unsigned long long dy = f2_add(yq[k], ncy);
            const unsigned long long dz = f2_add(zq[k], ncz);
            const unsigned long long s  =
                f2_add(f2_add(f2_mul(dx, dx), f2_mul(dy, dy)), f2_mul(dz, dz));
            float d0, d1;
            f2_unpack(d0, d1, s);
            pd[2*k]   = fminf(pd[2*k],   d0);
            pd[2*k+1] = fminf(pd[2*k+1], d1);
        }
        const float bestv = fmaxf(fmaxf(pd[0], pd[1]), fmaxf(pd[2], pd[3]));
        const unsigned bb = __float_as_uint(bestv);   // dists >= +0: u32 order == float order

        // --- warp argmax: one REDUX + ballot; lowest tied lane == first index ---
        const unsigned wmax = __reduce_max_sync(0xffffffffu, bb);
        const unsigned tied = __ballot_sync(0xffffffffu, bb == wmax);
        if (lane == __ffs(tied) - 1) {
            const float gm = __uint_as_float(wmax);
            int j = 0;
            #pragma unroll
            for (int jj = PPT - 1; jj >= 0; --jj)
                if (pd[jj] == gm) j = jj;              // first (smallest) j
            float lo, hi, sx, sy, sz;
            const unsigned long long xp = (j >> 1) ? xq[1] : xq[0];
            const unsigned long long yp = (j >> 1) ? yq[1] : yq[0];
            const unsigned long long zp = (j >> 1) ? zq[1] : zq[0];
            f2_unpack(lo, hi, xp); sx = (j & 1) ? hi : lo;
            f2_unpack(lo, hi, yp); sy = (j & 1) ? hi : lo;
            f2_unpack(lo, hi, zp); sz = (j & 1) ? hi : lo;
            s_wv[wid] = wmax;
            s_wi[wid] = base + j;
            s_cand[wid][0] = sx; s_cand[wid][1] = sy; s_cand[wid][2] = sz;
        }
        __syncthreads();

        if (wid == 0) {
            // --- CTA argmax over 16 warp entries; lowest tied warp == first index ---
            const unsigned bits = (lane < 16) ? s_wv[lane] : 0u;
            const unsigned m    = __reduce_max_sync(0xffffffffu, bits);
            const unsigned tw   = __ballot_sync(0xffffffffu, bits == m) & 0xffffu;
            const int src = __ffs(tw) - 1;

            if (lane < CLUSTER) {
                const unsigned cidx = (unsigned)s_wi[src];
                const float wx = s_cand[src][0];
                const float wy = s_cand[src][1];
                const float wz = s_cand[src][2];
                const uint32_t rem = slot ? remA1 : remA0;
                unsigned long long a = ((unsigned long long)cidx << 32) | m;
                unsigned long long c = ((unsigned long long)__float_as_uint(wy) << 32)
                                      | __float_as_uint(wx);
                asm volatile("st.shared::cluster.b64 [%0], %1;"    :: "r"(rem), "l"(a) : "memory");
                asm volatile("st.shared::cluster.b64 [%0+8], %1;"  :: "r"(rem), "l"(c) : "memory");
                asm volatile("st.shared::cluster.b32 [%0+16], %1;" :: "r"(rem),
                             "r"(__float_as_uint(wz)) : "memory");
            }
        }

        asm volatile("barrier.cluster.arrive.aligned;" ::: "memory");
        asm volatile("barrier.cluster.wait.aligned;"   ::: "memory");

        // every thread reduces the 8 mailbox entries (LDS broadcasts)
        unsigned bbits = 0u, bidx = 0xffffffffu, bx = 0, by = 0, bz = 0;
        #pragma unroll
        for (int r = 0; r < CLUSTER; r++) {
            const unsigned mb = mbox[slot][r][0];
            const unsigned mi = mbox[slot][r][1];
            const bool take = (mb > bbits) || (mb == bbits && mi < bidx);
            if (take) {
                bbits = mb; bidx = mi;
                bx = mbox[slot][r][2];
                by = mbox[slot][r][3];
                bz = mbox[slot][r][4];
            }
        }
        cx = __uint_as_float(bx);
        cy = __uint_as_float(by);
        cz = __uint_as_float(bz);

        if (rank == 0 && t == 0) {
            float* o = out_newxyz + ((size_t)b * NPT + it + 1) * 3;
            o[0] = cx; o[1] = cy; o[2] = cz;
        }
    }
}

// =================================================================================
// Kernel 2: feature transpose (B,C,N) -> (B,N,C), tiled 32x32 through smem.
// =================================================================================
__global__ void __launch_bounds__(256)
transpose_kernel(const float* __restrict__ feat)
{
    __shared__ float tile[32][33];
    const int b  = blockIdx.z;
    const int n0 = blockIdx.x * 32;
    const int c0 = blockIdx.y * 32;
    const int tx = threadIdx.x, ty = threadIdx.y;

    const float* src = feat + (size_t)b * NCH * N_PTS;
    #pragma unroll
    for (int i = 0; i < 32; i += 8)
        tile[ty + i][tx] = src[(size_t)(c0 + ty + i) * N_PTS + n0 + tx];
    __syncthreads();

    float* dst = g_featT + (size_t)b * N_PTS * NCH;
    #pragma unroll
    for (int i = 0; i < 32; i += 8)
        dst[(size_t)(n0 + ty + i) * NCH + c0 + tx] = tile[tx][ty + i];
}

// =================================================================================
// Kernel 3: ball query — one warp per centroid, early exit after K found.
// Distance matches the reference's expanded form: d = ((-2*dot) + s2) + n2.
// Qualify iff !(d > r^2); first K in index order; pad with first.
// =================================================================================
__global__ void __launch_bounds__(256)
ball_kernel(const float* __restrict__ xyz, const float* __restrict__ newxyz)
{
    const int wig    = (blockIdx.x * 256 + threadIdx.x) >> 5;   // b*512 + s
    const int lane   = threadIdx.x & 31;
    const int wlocal = threadIdx.x >> 5;
    __shared__ int sid[8][KNB];

    const int b = wig >> 9;
    const float* C = newxyz + (size_t)wig * 3;
    const float cx = C[0], cy = C[1], cz = C[2];
    const float s2 = __fadd_rn(__fadd_rn(__fmul_rn(cx,cx), __fmul_rn(cy,cy)), __fmul_rn(cz,cz));

    const float* X  = xyz  + (size_t)b * N_PTS * 3;
    const float* NN = g_n2 + (size_t)b * N_PTS;

    int cnt = 0;
    for (int basep = 0; basep < N_PTS && cnt < KNB; basep += 32) {
        const int p = basep + lane;
        const float x = X[3*p], y = X[3*p+1], z = X[3*p+2];
        float dot = __fmul_rn(cx, x);
        dot = __fmaf_rn(cy, y, dot);
        dot = __fmaf_rn(cz, z, dot);
        const float d = __fadd_rn(__fadd_rn(__fmul_rn(-2.0f, dot), s2), NN[p]);
        const bool q = !(d > R2);
        const unsigned m = __ballot_sync(0xffffffffu, q);
        const int pos = cnt + __popc(m & ((1u << lane) - 1u));
        if (q && pos < KNB) sid[wlocal][pos] = p;
        cnt += __popc(m);
    }
    __syncwarp();

    const int first = sid[wlocal][0];          // cnt==0 impossible: centroid itself qualifies
    const int v = (lane < cnt) ? sid[wlocal][lane] : first;
    g_idx[(size_t)wig * KNB + lane] = v;
}

// =================================================================================
// Kernel 4: masked max pool from transposed features — block per (b,s), thread=c.
// Warp lanes read consecutive channels -> fully coalesced 128B gathers.
// =================================================================================
__global__ void __launch_bounds__(128)
pool_kernel(float* __restrict__ out)
{
    const int g = blockIdx.x;             // b*512 + s
    const int c = threadIdx.x;
    const int b = g >> 9;
    const int s = g & 511;

    __shared__ int nb[KNB];
    if (c < KNB) nb[c] = g_idx[(size_t)g * KNB + c];
    __syncthreads();

    const float* F = g_featT + (size_t)b * N_PTS * NCH;

    float m0 = F[(size_t)nb[0] * NCH + c];
    float m1 = F[(size_t)nb[1] * NCH + c];
    float m2 = F[(size_t)nb[2] * NCH + c];
    float m3 = F[(size_t)nb[3] * NCH + c];
    #pragma unroll
    for (int k = 4; k < KNB; k += 4) {
        m0 = fmaxf(m0, F[(size_t)nb[k]   * NCH + c]);
        m1 = fmaxf(m1, F[(size_t)nb[k+1] * NCH + c]);
        m2 = fmaxf(m2, F[(size_t)nb[k+2] * NCH + c]);
        m3 = fmaxf(m3, F[(size_t)nb[k+3] * NCH + c]);
    }
    const float m = fmaxf(fmaxf(m0, m1), fmaxf(m2, m3));

    out[(size_t)B_SZ*NPT*3 + ((size_t)b * NCH + c) * NPT + s] = m;
}

// =================================================================================
extern "C" void kernel_launch(void* const* d_in, const int* in_sizes, int n_in,
                              void* d_out, int out_size)
{
    const float* xyz  = (const float*)d_in[0];   // (8, 16384, 3) fp32
    const float* feat = (const float*)d_in[1];   // (8, 128, 16384) fp32
    float* out = (float*)d_out;                  // new_xyz (12288) ++ sub_features (524288)

    dim3 tgrid(N_PTS / 32, NCH / 32, B_SZ);
    dim3 tblk(32, 8);
    transpose_kernel<<<tgrid, tblk>>>(feat);

    dim3 fgrid(CLUSTER, B_SZ);
    fps_kernel<<<fgrid, FPS_THR>>>(xyz, out);

    ball_kernel<<<(B_SZ * NPT * 32) / 256, 256>>>(xyz, out);
    pool_kernel<<<B_SZ * NPT, 128>>>(out);
}

// round 15
// speedup vs baseline: 1.3665x; 1.2465x over previous
#include <cuda_runtime.h>
#include <cstdint>

#define N_PTS   16384
#define B_SZ    8
#define NPT     512
#define KNB     32
#define NCH     128
#define R2      0.04f

#define CLUSTER 8
#define PTS_PER_CTA (N_PTS / CLUSTER)   // 2048
#define FPS_THR 512
#define PPT (PTS_PER_CTA / FPS_THR)     // 4 points per thread
#define MSG_BYTES 20                    // bits,idx,x,y,z per rank
#define PHASE_TX (CLUSTER * MSG_BYTES)  // 160 bytes expected per phase

// ---------------- device scratch (no runtime allocation allowed) ----------------
__device__ float g_n2   [B_SZ * N_PTS];               // per-point squared norms
__device__ int   g_idx  [B_SZ * NPT * KNB];           // ball-query neighbor lists
__device__ float g_featT[(size_t)B_SZ * N_PTS * NCH]; // features transposed to (B,N,C)

// ---------------- packed f32x2 helpers (two independent IEEE-rn ops) ------------
__device__ __forceinline__ unsigned long long f2_add(unsigned long long a, unsigned long long b) {
    unsigned long long r; asm("add.rn.f32x2 %0, %1, %2;" : "=l"(r) : "l"(a), "l"(b)); return r;
}
__device__ __forceinline__ unsigned long long f2_mul(unsigned long long a, unsigned long long b) {
    unsigned long long r; asm("mul.rn.f32x2 %0, %1, %2;" : "=l"(r) : "l"(a), "l"(b)); return r;
}
__device__ __forceinline__ unsigned long long f2_pack(float lo, float hi) {
    unsigned long long r; asm("mov.b64 %0, {%1, %2};" : "=l"(r) : "f"(lo), "f"(hi)); return r;
}
__device__ __forceinline__ void f2_unpack(float& lo, float& hi, unsigned long long v) {
    asm("mov.b64 {%0, %1}, %2;" : "=f"(lo), "=f"(hi) : "l"(v));
}
__device__ __forceinline__ uint32_t smem_u32(const void* p) {
    uint32_t a;
    asm("{ .reg .u64 t; cvta.to.shared.u64 t, %1; cvt.u32.u64 %0, t; }" : "=r"(a) : "l"(p));
    return a;
}
// acquire parity wait on a LOCAL mbarrier (HW sleep; data published by st.async
// complete_tx is visible to threads observing the phase flip with acquire)
__device__ __forceinline__ void mbar_wait(uint32_t mbar, uint32_t parity) {
    uint32_t done;
    asm volatile(
        "{\n\t.reg .pred p;\n\t"
        "mbarrier.try_wait.parity.acquire.cluster.shared::cta.b64 p, [%1], %2;\n\t"
        "selp.b32 %0, 1, 0, p;\n\t}"
        : "=r"(done) : "r"(mbar), "r"(parity) : "memory");
    if (!done) {
        asm volatile(
            "{\n\t.reg .pred P1;\n\t"
            "WL_%=:\n\t"
            "mbarrier.try_wait.parity.acquire.cluster.shared::cta.b64 P1, [%0], %1, 0x989680;\n\t"
            "@P1 bra.uni WD_%=;\n\t"
            "bra.uni WL_%=;\n\t"
            "WD_%=:\n\t}"
            :: "r"(mbar), "r"(parity) : "memory");
    }
}

// =================================================================================
// Kernel 1: FPS — cluster of 8 CTAs per batch, 512 thr/CTA, 4 pts/thread in
// registers (f32x2-packed). Exchange = st.async fused store+complete_tx into every
// peer's mailbox + local mbarrier (count=1, expect_tx=160B/phase, re-armed by t0
// after each wait). Sender posts and never waits; receiver wakes on its LOCAL
// barrier — no cluster-wide barrier, no L1 flush, no remote RMW serialization.
// Slot reuse safe: sends@it+1 happen after __syncthreads@it+1 (all local reads of
// mbox@it done); peers' writes@it+2 require our tx@it+1.
// Arithmetic + tie-break identical to the rel_err==0 baseline.
// =================================================================================
__global__ void __launch_bounds__(FPS_THR, 1) __cluster_dims__(CLUSTER, 1, 1)
fps_kernel(const float* __restrict__ xyz, float* __restrict__ out_newxyz)
{
    const int rank = blockIdx.x;          // CTA rank within cluster (0..7)
    const int b    = blockIdx.y;          // batch
    const int t    = threadIdx.x;
    const int lane = t & 31;
    const int wid  = t >> 5;              // 0..15

    const float* X = xyz + (size_t)b * N_PTS * 3;

    __shared__ unsigned s_wv[16];
    __shared__ int      s_wi[16];
    __shared__ float    s_cand[16][3];
    __shared__ alignas(8) unsigned mbox[2][CLUSTER][6]; // bits, idx, x, y, z, pad
    __shared__ alignas(8) unsigned long long s_bar[2];  // mbarriers (count = 1)

    const int base = rank * PTS_PER_CTA + t * PPT;      // first owned global point

    if (t == 0) {
        const uint32_t m0 = smem_u32(&s_bar[0]);
        const uint32_t m1 = smem_u32(&s_bar[1]);
        asm volatile("mbarrier.init.shared.b64 [%0], 1;" :: "r"(m0) : "memory");
        asm volatile("mbarrier.init.shared.b64 [%0], 1;" :: "r"(m1) : "memory");
    }

    // ---- load 4 points (12 floats = 3x float4, 48B-aligned) ----
    const float4 q0 = *(const float4*)(X + (size_t)base * 3);
    const float4 q1 = *(const float4*)(X + (size_t)base * 3 + 4);
    const float4 q2 = *(const float4*)(X + (size_t)base * 3 + 8);
    const float ax0 = q0.x, ay0 = q0.y, az0 = q0.z;
    const float ax1 = q0.w, ay1 = q1.x, az1 = q1.y;
    const float ax2 = q1.z, ay2 = q1.w, az2 = q2.x;
    const float ax3 = q2.y, ay3 = q2.z, az3 = q2.w;

    // squared norms for the ball-query kernel (exact square-then-sum)
    {
        float4 n;
        n.x = __fadd_rn(__fadd_rn(__fmul_rn(ax0,ax0), __fmul_rn(ay0,ay0)), __fmul_rn(az0,az0));
        n.y = __fadd_rn(__fadd_rn(__fmul_rn(ax1,ax1), __fmul_rn(ay1,ay1)), __fmul_rn(az1,az1));
        n.z = __fadd_rn(__fadd_rn(__fmul_rn(ax2,ax2), __fmul_rn(ay2,ay2)), __fmul_rn(az2,az2));
        n.w = __fadd_rn(__fadd_rn(__fmul_rn(ax3,ax3), __fmul_rn(ay3,ay3)), __fmul_rn(az3,az3));
        *(float4*)(g_n2 + (size_t)b * N_PTS + base) = n;
    }

    unsigned long long xq[2], yq[2], zq[2];
    xq[0] = f2_pack(ax0, ax1); xq[1] = f2_pack(ax2, ax3);
    yq[0] = f2_pack(ay0, ay1); yq[1] = f2_pack(ay2, ay3);
    zq[0] = f2_pack(az0, az1); zq[1] = f2_pack(az2, az3);
    float pd[4] = {1e10f, 1e10f, 1e10f, 1e10f};

    // hoisted remote mailbox + barrier addresses (warp0 lanes 0..7 push)
    uint32_t remM0 = 0, remM1 = 0, remB0 = 0, remB1 = 0;
    if (wid == 0 && lane < CLUSTER) {
        const uint32_t l0 = smem_u32(&mbox[0][rank][0]);
        const uint32_t l1 = smem_u32(&mbox[1][rank][0]);
        const uint32_t b0 = smem_u32(&s_bar[0]);
        const uint32_t b1 = smem_u32(&s_bar[1]);
        asm("mapa.shared::cluster.u32 %0, %1, %2;" : "=r"(remM0) : "r"(l0), "r"(lane));
        asm("mapa.shared::cluster.u32 %0, %1, %2;" : "=r"(remM1) : "r"(l1), "r"(lane));
        asm("mapa.shared::cluster.u32 %0, %1, %2;" : "=r"(remB0) : "r"(b0), "r"(lane));
        asm("mapa.shared::cluster.u32 %0, %1, %2;" : "=r"(remB1) : "r"(b1), "r"(lane));
    }

    float cx = __ldg(X + 0), cy = __ldg(X + 1), cz = __ldg(X + 2);
    if (rank == 0 && t == 0) {
        float* o = out_newxyz + (size_t)b * NPT * 3;
        o[0] = cx; o[1] = cy; o[2] = cz;
    }

    // inits visible cluster-wide before any remote st.async, then arm both slots
    __syncthreads();
    asm volatile("barrier.cluster.arrive.aligned;" ::: "memory");
    asm volatile("barrier.cluster.wait.aligned;"   ::: "memory");
    if (t == 0) {
        asm volatile("mbarrier.arrive.expect_tx.shared.b64 _, [%0], %1;"
                     :: "r"(smem_u32(&s_bar[0])), "r"(PHASE_TX) : "memory");
        asm volatile("mbarrier.arrive.expect_tx.shared.b64 _, [%0], %1;"
                     :: "r"(smem_u32(&s_bar[1])), "r"(PHASE_TX) : "memory");
    }

    for (int it = 0; it < NPT - 1; ++it) {
        const int      slot  = it & 1;
        const unsigned phase = (unsigned)((it >> 1) & 1);

        const unsigned long long ncx = f2_pack(-cx, -cx);
        const unsigned long long ncy = f2_pack(-cy, -cy);
        const unsigned long long ncz = f2_pack(-cz, -cz);

        #pragma unroll
        for (int k = 0; k < 2; k++) {
            const unsigned long long dx = f2_add(xq[k], ncx);
            const unsigned long long dy = f2_add(yq[k], ncy);
            const unsigned long long dz = f2_add(zq[k], ncz);
            const unsigned long long s  =
                f2_add(f2_add(f2_mul(dx, dx), f2_mul(dy, dy)), f2_mul(dz, dz));
            float d0, d1;
            f2_unpack(d0, d1, s);
            pd[2*k]   = fminf(pd[2*k],   d0);
            pd[2*k+1] = fminf(pd[2*k+1], d1);
        }
        const float bestv = fmaxf(fmaxf(pd[0], pd[1]), fmaxf(pd[2], pd[3]));
        const unsigned bb = __float_as_uint(bestv);   // dists >= +0: u32 order == float order

        // --- warp argmax: one REDUX + ballot; lowest tied lane == first index ---
        const unsigned wmax = __reduce_max_sync(0xffffffffu, bb);
        const unsigned tied = __ballot_sync(0xffffffffu, bb == wmax);
        if (lane == __ffs(tied) - 1) {
            const float gm = __uint_as_float(wmax);
            int j = 0;
            #pragma unroll
            for (int jj = PPT - 1; jj >= 0; --jj)
                if (pd[jj] == gm) j = jj;              // first (smallest) j
            float lo, hi, sx, sy, sz;
            const unsigned long long xp = (j >> 1) ? xq[1] : xq[0];
            const unsigned long long yp = (j >> 1) ? yq[1] : yq[0];
            const unsigned long long zp = (j >> 1) ? zq[1] : zq[0];
            f2_unpack(lo, hi, xp); sx = (j & 1) ? hi : lo;
            f2_unpack(lo, hi, yp); sy = (j & 1) ? hi : lo;
            f2_unpack(lo, hi, zp); sz = (j & 1) ? hi : lo;
            s_wv[wid] = wmax;
            s_wi[wid] = base + j;
            s_cand[wid][0] = sx; s_cand[wid][1] = sy; s_cand[wid][2] = sz;
        }
        __syncthreads();

        if (wid == 0) {
            // --- CTA argmax over 16 warp entries; lowest tied warp == first index ---
            const unsigned bits = (lane < 16) ? s_wv[lane] : 0u;
            const unsigned m    = __reduce_max_sync(0xffffffffu, bits);
            const unsigned tw   = __ballot_sync(0xffffffffu, bits == m) & 0xffffu;
            const int src = __ffs(tw) - 1;

            if (lane < CLUSTER) {
                const unsigned cidx = (unsigned)s_wi[src];
                const float wx = s_cand[src][0];
                const float wy = s_cand[src][1];
                const float wz = s_cand[src][2];
                const uint32_t remM = slot ? remM1 : remM0;
                const uint32_t remB = slot ? remB1 : remB0;
                unsigned long long a = ((unsigned long long)cidx << 32) | m;
                unsigned long long c = ((unsigned long long)__float_as_uint(wy) << 32)
                                      | __float_as_uint(wx);
                // fused store + tx-signal; posted, sender never waits
                asm volatile("st.async.shared::cluster.mbarrier::complete_tx::bytes.b64 [%0], %1, [%2];"
                             :: "r"(remM), "l"(a), "r"(remB) : "memory");
                asm volatile("st.async.shared::cluster.mbarrier::complete_tx::bytes.b64 [%0], %1, [%2];"
                             :: "r"(remM + 8), "l"(c), "r"(remB) : "memory");
                asm volatile("st.async.shared::cluster.mbarrier::complete_tx::bytes.b32 [%0], %1, [%2];"
                             :: "r"(remM + 16), "r"(__float_as_uint(wz)), "r"(remB) : "memory");
            }
        }

        // wait on LOCAL barrier for all 160 tx bytes of this slot/phase
        mbar_wait(smem_u32(&s_bar[slot]), phase);
        if (t == 0) {   // re-arm this slot for its use at it+2
            asm volatile("mbarrier.arrive.expect_tx.shared.b64 _, [%0], %1;"
                         :: "r"(smem_u32(&s_bar[slot])), "r"(PHASE_TX) : "memory");
        }

        // every thread reduces the 8 mailbox entries (LDS broadcasts)
        unsigned bbits = 0u, bidx = 0xffffffffu, bx = 0, by = 0, bz = 0;
        #pragma unroll
        for (int r = 0; r < CLUSTER; r++) {
            const unsigned mb = mbox[slot][r][0];
            const unsigned mi = mbox[slot][r][1];
            const bool take = (mb > bbits) || (mb == bbits && mi < bidx);
            if (take) {
                bbits = mb; bidx = mi;
                bx = mbox[slot][r][2];
                by = mbox[slot][r][3];
                bz = mbox[slot][r][4];
            }
        }
        cx = __uint_as_float(bx);
        cy = __uint_as_float(by);
        cz = __uint_as_float(bz);

        if (rank == 0 && t == 0) {
            float* o = out_newxyz + ((size_t)b * NPT + it + 1) * 3;
            o[0] = cx; o[1] = cy; o[2] = cz;
        }
    }

    // keep cluster alive until all in-flight st.async / final reads complete
    asm volatile("barrier.cluster.arrive.aligned;" ::: "memory");
    asm volatile("barrier.cluster.wait.aligned;"   ::: "memory");
}

// =================================================================================
// Kernel 2: feature transpose (B,C,N) -> (B,N,C), tiled 32x32 through smem.
// =================================================================================
__global__ void __launch_bounds__(256)
transpose_kernel(const float* __restrict__ feat)
{
    __shared__ float tile[32][33];
    const int b  = blockIdx.z;
    const int n0 = blockIdx.x * 32;
    const int c0 = blockIdx.y * 32;
    const int tx = threadIdx.x, ty = threadIdx.y;

    const float* src = feat + (size_t)b * NCH * N_PTS;
    #pragma unroll
    for (int i = 0; i < 32; i += 8)
        tile[ty + i][tx] = src[(size_t)(c0 + ty + i) * N_PTS + n0 + tx];
    __syncthreads();

    float* dst = g_featT + (size_t)b * N_PTS * NCH;
    #pragma unroll
    for (int i = 0; i < 32; i += 8)
        dst[(size_t)(n0 + ty + i) * NCH + c0 + tx] = tile[tx][ty + i];
}

// =================================================================================
// Kernel 3: ball query — one warp per centroid, early exit after K found.
// Distance matches the reference's expanded form: d = ((-2*dot) + s2) + n2.
// Qualify iff !(d > r^2); first K in index order; pad with first.
// =================================================================================
__global__ void __launch_bounds__(256)
ball_kernel(const float* __restrict__ xyz, const float* __restrict__ newxyz)
{
    const int wig    = (blockIdx.x * 256 + threadIdx.x) >> 5;   // b*512 + s
    const int lane   = threadIdx.x & 31;
    const int wlocal = threadIdx.x >> 5;
    __shared__ int sid[8][KNB];

    const int b = wig >> 9;
    const float* C = newxyz + (size_t)wig * 3;
    const float cx = C[0], cy = C[1], cz = C[2];
    const float s2 = __fadd_rn(__fadd_rn(__fmul_rn(cx,cx), __fmul_rn(cy,cy)), __fmul_rn(cz,cz));

    const float* X  = xyz  + (size_t)b * N_PTS * 3;
    const float* NN = g_n2 + (size_t)b * N_PTS;

    int cnt = 0;
    for (int basep = 0; basep < N_PTS && cnt < KNB; basep += 32) {
        const int p = basep + lane;
        const float x = X[3*p], y = X[3*p+1], z = X[3*p+2];
        float dot = __fmul_rn(cx, x);
        dot = __fmaf_rn(cy, y, dot);
        dot = __fmaf_rn(cz, z, dot);
        const float d = __fadd_rn(__fadd_rn(__fmul_rn(-2.0f, dot), s2), NN[p]);
        const bool q = !(d > R2);
        const unsigned m = __ballot_sync(0xffffffffu, q);
        const int pos = cnt + __popc(m & ((1u << lane) - 1u));
        if (q && pos < KNB) sid[wlocal][pos] = p;
        cnt += __popc(m);
    }
    __syncwarp();

    const int first = sid[wlocal][0];          // cnt==0 impossible: centroid itself qualifies
    const int v = (lane < cnt) ? sid[wlocal][lane] : first;
    g_idx[(size_t)wig * KNB + lane] = v;
}

// =================================================================================
// Kernel 4: masked max pool from transposed features — block per (b,s), thread=c.
// Warp lanes read consecutive channels -> fully coalesced 128B gathers.
// =================================================================================
__global__ void __launch_bounds__(128)
pool_kernel(float* __restrict__ out)
{
    const int g = blockIdx.x;             // b*512 + s
    const int c = threadIdx.x;
    const int b = g >> 9;
    const int s = g & 511;

    __shared__ int nb[KNB];
    if (c < KNB) nb[c] = g_idx[(size_t)g * KNB + c];
    __syncthreads();

    const float* F = g_featT + (size_t)b * N_PTS * NCH;

    float m0 = F[(size_t)nb[0] * NCH + c];
    float m1 = F[(size_t)nb[1] * NCH + c];
    float m2 = F[(size_t)nb[2] * NCH + c];
    float m3 = F[(size_t)nb[3] * NCH + c];
    #pragma unroll
    for (int k = 4; k < KNB; k += 4) {
        m0 = fmaxf(m0, F[(size_t)nb[k]   * NCH + c]);
        m1 = fmaxf(m1, F[(size_t)nb[k+1] * NCH + c]);
        m2 = fmaxf(m2, F[(size_t)nb[k+2] * NCH + c]);
        m3 = fmaxf(m3, F[(size_t)nb[k+3] * NCH + c]);
    }
    const float m = fmaxf(fmaxf(m0, m1), fmaxf(m2, m3));

    out[(size_t)B_SZ*NPT*3 + ((size_t)b * NCH + c) * NPT + s] = m;
}

// =================================================================================
extern "C" void kernel_launch(void* const* d_in, const int* in_sizes, int n_in,
                              void* d_out, int out_size)
{
    const float* xyz  = (const float*)d_in[0];   // (8, 16384, 3) fp32
    const float* feat = (const float*)d_in[1];   // (8, 128, 16384) fp32
    float* out = (float*)d_out;                  // new_xyz (12288) ++ sub_features (524288)

    dim3 tgrid(N_PTS / 32, NCH / 32, B_SZ);
    dim3 tblk(32, 8);
    transpose_kernel<<<tgrid, tblk>>>(feat);

    dim3 fgrid(CLUSTER, B_SZ);
    fps_kernel<<<fgrid, FPS_THR>>>(xyz, out);

    ball_kernel<<<(B_SZ * NPT * 32) / 256, 256>>>(xyz, out);
    pool_kernel<<<B_SZ * NPT, 128>>>(out);
}

// round 17
// speedup vs baseline: 1.5060x; 1.1021x over previous
#include <cuda_runtime.h>
#include <cstdint>

#define N_PTS   16384
#define B_SZ    8
#define NPT     512
#define KNB     32
#define NCH     128
#define R2      0.04f

#define CLUSTER 8
#define PTS_PER_CTA (N_PTS / CLUSTER)   // 2048
#define FPS_THR 512
#define PPT (PTS_PER_CTA / FPS_THR)     // 4 points per thread
#define MSG_BYTES 20                    // key(8), xy(8), z(4) per rank
#define PHASE_TX (CLUSTER * MSG_BYTES)  // 160 bytes expected per phase

// ---------------- device scratch (no runtime allocation allowed) ----------------
__device__ float g_n2   [B_SZ * N_PTS];               // per-point squared norms
__device__ int   g_idx  [B_SZ * NPT * KNB];           // ball-query neighbor lists
__device__ float g_featT[(size_t)B_SZ * N_PTS * NCH]; // features transposed to (B,N,C)

// ---------------- packed f32x2 helpers (two independent IEEE-rn ops) ------------
__device__ __forceinline__ unsigned long long f2_add(unsigned long long a, unsigned long long b) {
    unsigned long long r; asm("add.rn.f32x2 %0, %1, %2;" : "=l"(r) : "l"(a), "l"(b)); return r;
}
__device__ __forceinline__ unsigned long long f2_mul(unsigned long long a, unsigned long long b) {
    unsigned long long r; asm("mul.rn.f32x2 %0, %1, %2;" : "=l"(r) : "l"(a), "l"(b)); return r;
}
__device__ __forceinline__ unsigned long long f2_pack(float lo, float hi) {
    unsigned long long r; asm("mov.b64 %0, {%1, %2};" : "=l"(r) : "f"(lo), "f"(hi)); return r;
}
__device__ __forceinline__ void f2_unpack(float& lo, float& hi, unsigned long long v) {
    asm("mov.b64 {%0, %1}, %2;" : "=f"(lo), "=f"(hi) : "l"(v));
}
__device__ __forceinline__ uint32_t smem_u32(const void* p) {
    uint32_t a;
    asm("{ .reg .u64 t; cvta.to.shared.u64 t, %1; cvt.u32.u64 %0, t; }" : "=r"(a) : "l"(p));
    return a;
}
__device__ __forceinline__ unsigned long long u64max(unsigned long long a, unsigned long long b) {
    return a > b ? a : b;
}
// acquire parity wait on a LOCAL mbarrier (HW sleep; data published by st.async
// complete_tx is visible to threads observing the phase flip with acquire)
__device__ __forceinline__ void mbar_wait(uint32_t mbar, uint32_t parity) {
    uint32_t done;
    asm volatile(
        "{\n\t.reg .pred p;\n\t"
        "mbarrier.try_wait.parity.acquire.cluster.shared::cta.b64 p, [%1], %2;\n\t"
        "selp.b32 %0, 1, 0, p;\n\t}"
        : "=r"(done) : "r"(mbar), "r"(parity) : "memory");
    if (!done) {
        asm volatile(
            "{\n\t.reg .pred P1;\n\t"
            "WL_%=:\n\t"
            "mbarrier.try_wait.parity.acquire.cluster.shared::cta.b64 P1, [%0], %1, 0x989680;\n\t"
            "@P1 bra.uni WD_%=;\n\t"
            "bra.uni WL_%=;\n\t"
            "WD_%=:\n\t}"
            :: "r"(mbar), "r"(parity) : "memory");
    }
}

// =================================================================================
// Kernel 1: FPS — cluster of 8 CTAs per batch, 512 thr/CTA, 4 pts/thread in
// registers (f32x2-packed). Exchange = st.async fused store+complete_tx into every
// peer's mailbox + local mbarrier (count=1, expect_tx=160B/phase).
// R15 deltas vs the 475us baseline (protocol and arithmetic unchanged):
//   * mailbox word0 is a u64 key = (bits<<32) | (16383 - idx): receiver reduce is
//     8x LDS.64 + 3-deep u64-max tree (max key == max bits, tie -> min idx, same
//     tie-break); winner rank = idx>>11 (ranks own contiguous 2048-pt blocks),
//     coords fetched by 3 broadcast LDS.
//   * split named barrier: warps 1..15 bar.arrive and go straight to the mbarrier
//     wait; only warp0 bar.sync's, selects, and sends. Waking from the mbarrier
//     implies own warp0 already read s_wv (own 20 tx bytes are sent after that
//     read), so next-iteration overwrites of s_wv are ordered.
// =================================================================================
__global__ void __launch_bounds__(FPS_THR, 1) __cluster_dims__(CLUSTER, 1, 1)
fps_kernel(const float* __restrict__ xyz, float* __restrict__ out_newxyz)
{
    const int rank = blockIdx.x;          // CTA rank within cluster (0..7)
    const int b    = blockIdx.y;          // batch
    const int t    = threadIdx.x;
    const int lane = t & 31;
    const int wid  = t >> 5;              // 0..15

    const float* X = xyz + (size_t)b * N_PTS * 3;

    __shared__ unsigned s_wv[16];
    __shared__ int      s_wi[16];
    __shared__ float    s_cand[16][3];
    __shared__ alignas(8) unsigned mbox[2][CLUSTER][6]; // key(2), x, y, z, pad
    __shared__ alignas(8) unsigned long long s_bar[2];  // mbarriers (count = 1)

    const int base = rank * PTS_PER_CTA + t * PPT;      // first owned global point

    if (t == 0) {
        const uint32_t m0 = smem_u32(&s_bar[0]);
        const uint32_t m1 = smem_u32(&s_bar[1]);
        asm volatile("mbarrier.init.shared.b64 [%0], 1;" :: "r"(m0) : "memory");
        asm volatile("mbarrier.init.shared.b64 [%0], 1;" :: "r"(m1) : "memory");
    }

    // ---- load 4 points (12 floats = 3x float4, 48B-aligned) ----
    const float4 q0 = *(const float4*)(X + (size_t)base * 3);
    const float4 q1 = *(const float4*)(X + (size_t)base * 3 + 4);
    const float4 q2 = *(const float4*)(X + (size_t)base * 3 + 8);
    const float ax0 = q0.x, ay0 = q0.y, az0 = q0.z;
    const float ax1 = q0.w, ay1 = q1.x, az1 = q1.y;
    const float ax2 = q1.z, ay2 = q1.w, az2 = q2.x;
    const float ax3 = q2.y, ay3 = q2.z, az3 = q2.w;

    // squared norms for the ball-query kernel (exact square-then-sum)
    {
        float4 n;
        n.x = __fadd_rn(__fadd_rn(__fmul_rn(ax0,ax0), __fmul_rn(ay0,ay0)), __fmul_rn(az0,az0));
        n.y = __fadd_rn(__fadd_rn(__fmul_rn(ax1,ax1), __fmul_rn(ay1,ay1)), __fmul_rn(az1,az1));
        n.z = __fadd_rn(__fadd_rn(__fmul_rn(ax2,ax2), __fmul_rn(ay2,ay2)), __fmul_rn(az2,az2));
        n.w = __fadd_rn(__fadd_rn(__fmul_rn(ax3,ax3), __fmul_rn(ay3,ay3)), __fmul_rn(az3,az3));
        *(float4*)(g_n2 + (size_t)b * N_PTS + base) = n;
    }

    unsigned long long xq[2], yq[2], zq[2];
    xq[0] = f2_pack(ax0, ax1); xq[1] = f2_pack(ax2, ax3);
    yq[0] = f2_pack(ay0, ay1); yq[1] = f2_pack(ay2, ay3);
    zq[0] = f2_pack(az0, az1); zq[1] = f2_pack(az2, az3);
    float pd[4] = {1e10f, 1e10f, 1e10f, 1e10f};

    // hoisted remote mailbox + barrier addresses (warp0 lanes 0..7 push)
    uint32_t remM0 = 0, remM1 = 0, remB0 = 0, remB1 = 0;
    if (wid == 0 && lane < CLUSTER) {
        const uint32_t l0 = smem_u32(&mbox[0][rank][0]);
        const uint32_t l1 = smem_u32(&mbox[1][rank][0]);
        const uint32_t b0 = smem_u32(&s_bar[0]);
        const uint32_t b1 = smem_u32(&s_bar[1]);
        asm("mapa.shared::cluster.u32 %0, %1, %2;" : "=r"(remM0) : "r"(l0), "r"(lane));
        asm("mapa.shared::cluster.u32 %0, %1, %2;" : "=r"(remM1) : "r"(l1), "r"(lane));
        asm("mapa.shared::cluster.u32 %0, %1, %2;" : "=r"(remB0) : "r"(b0), "r"(lane));
        asm("mapa.shared::cluster.u32 %0, %1, %2;" : "=r"(remB1) : "r"(b1), "r"(lane));
    }

    float cx = __ldg(X + 0), cy = __ldg(X + 1), cz = __ldg(X + 2);
    if (rank == 0 && t == 0) {
        float* o = out_newxyz + (size_t)b * NPT * 3;
        o[0] = cx; o[1] = cy; o[2] = cz;
    }

    // inits visible cluster-wide before any remote st.async, then arm both slots
    __syncthreads();
    asm volatile("barrier.cluster.arrive.aligned;" ::: "memory");
    asm volatile("barrier.cluster.wait.aligned;"   ::: "memory");
    if (t == 0) {
        asm volatile("mbarrier.arrive.expect_tx.shared.b64 _, [%0], %1;"
                     :: "r"(smem_u32(&s_bar[0])), "r"(PHASE_TX) : "memory");
        asm volatile("mbarrier.arrive.expect_tx.shared.b64 _, [%0], %1;"
                     :: "r"(smem_u32(&s_bar[1])), "r"(PHASE_TX) : "memory");
    }

    for (int it = 0; it < NPT - 1; ++it) {
        const int      slot  = it & 1;
        const unsigned phase = (unsigned)((it >> 1) & 1);

        const unsigned long long ncx = f2_pack(-cx, -cx);
        const unsigned long long ncy = f2_pack(-cy, -cy);
        const unsigned long long ncz = f2_pack(-cz, -cz);

        #pragma unroll
        for (int k = 0; k < 2; k++) {
            const unsigned long long dx = f2_add(xq[k], ncx);
            const unsigned long long dy = f2_add(yq[k], ncy);
            const unsigned long long dz = f2_add(zq[k], ncz);
            const unsigned long long s  =
                f2_add(f2_add(f2_mul(dx, dx), f2_mul(dy, dy)), f2_mul(dz, dz));
            float d0, d1;
            f2_unpack(d0, d1, s);
            pd[2*k]   = fminf(pd[2*k],   d0);
            pd[2*k+1] = fminf(pd[2*k+1], d1);
        }
        const float bestv = fmaxf(fmaxf(pd[0], pd[1]), fmaxf(pd[2], pd[3]));
        const unsigned bb = __float_as_uint(bestv);   // dists >= +0: u32 order == float order

        // --- warp argmax: one REDUX + ballot; lowest tied lane == first index ---
        const unsigned wmax = __reduce_max_sync(0xffffffffu, bb);
        const unsigned tied = __ballot_sync(0xffffffffu, bb == wmax);
        if (lane == __ffs(tied) - 1) {
            const float gm = __uint_as_float(wmax);
            int j = 0;
            #pragma unroll
            for (int jj = PPT - 1; jj >= 0; --jj)
                if (pd[jj] == gm) j = jj;              // first (smallest) j
            float lo, hi, sx, sy, sz;
            const unsigned long long xp = (j >> 1) ? xq[1] : xq[0];
            const unsigned long long yp = (j >> 1) ? yq[1] : yq[0];
            const unsigned long long zp = (j >> 1) ? zq[1] : zq[0];
            f2_unpack(lo, hi, xp); sx = (j & 1) ? hi : lo;
            f2_unpack(lo, hi, yp); sy = (j & 1) ? hi : lo;
            f2_unpack(lo, hi, zp); sz = (j & 1) ? hi : lo;
            s_wv[wid] = wmax;
            s_wi[wid] = base + j;
            s_cand[wid][0] = sx; s_cand[wid][1] = sy; s_cand[wid][2] = sz;
        }

        // split named barrier: producers arrive and go wait; only warp0 syncs
        if (wid == 0) {
            asm volatile("bar.sync 1, %0;" :: "r"(FPS_THR) : "memory");

            // --- CTA argmax over 16 warp entries; lowest tied warp == first index ---
            const unsigned bits = (lane < 16) ? s_wv[lane] : 0u;
            const unsigned m    = __reduce_max_sync(0xffffffffu, bits);
            const unsigned tw   = __ballot_sync(0xffffffffu, bits == m) & 0xffffu;
            const int src = __ffs(tw) - 1;

            if (lane < CLUSTER) {
                const unsigned cidx = (unsigned)s_wi[src];
                const float wx = s_cand[src][0];
                const float wy = s_cand[src][1];
                const float wz = s_cand[src][2];
                const uint32_t remM = slot ? remM1 : remM0;
                const uint32_t remB = slot ? remB1 : remB0;
                // key: max over keys == (max bits, tie -> min idx)
                const unsigned long long key =
                    ((unsigned long long)m << 32) | (unsigned)(16383 - (int)cidx);
                const unsigned long long c =
                    ((unsigned long long)__float_as_uint(wy) << 32) | __float_as_uint(wx);
                asm volatile("st.async.shared::cluster.mbarrier::complete_tx::bytes.b64 [%0], %1, [%2];"
                             :: "r"(remM), "l"(key), "r"(remB) : "memory");
                asm volatile("st.async.shared::cluster.mbarrier::complete_tx::bytes.b64 [%0], %1, [%2];"
                             :: "r"(remM + 8), "l"(c), "r"(remB) : "memory");
                asm volatile("st.async.shared::cluster.mbarrier::complete_tx::bytes.b32 [%0], %1, [%2];"
                             :: "r"(remM + 16), "r"(__float_as_uint(wz)), "r"(remB) : "memory");
            }
        } else {
            asm volatile("bar.arrive 1, %0;" :: "r"(FPS_THR) : "memory");
        }

        // wait on LOCAL barrier for all 160 tx bytes of this slot/phase
        mbar_wait(smem_u32(&s_bar[slot]), phase);
        if (t == 0) {   // re-arm this slot for its use at it+2
            asm volatile("mbarrier.arrive.expect_tx.shared.b64 _, [%0], %1;"
                         :: "r"(smem_u32(&s_bar[slot])), "r"(PHASE_TX) : "memory");
        }

        // reduce 8 u64 keys with a 3-deep max tree (LDS.64 broadcasts)
        unsigned long long kk[CLUSTER];
        #pragma unroll
        for (int r = 0; r < CLUSTER; r++)
            kk[r] = *(const unsigned long long*)&mbox[slot][r][0];
        const unsigned long long best =
            u64max(u64max(u64max(kk[0], kk[1]), u64max(kk[2], kk[3])),
                   u64max(u64max(kk[4], kk[5]), u64max(kk[6], kk[7])));
        const int widx = 16383 - (int)(best & 0x3fffu);
        const int rwin = widx >> 11;                  // ranks own contiguous 2048-pt blocks
        cx = __uint_as_float(mbox[slot][rwin][2]);
        cy = __uint_as_float(mbox[slot][rwin][3]);
        cz = __uint_as_float(mbox[slot][rwin][4]);

        if (rank == 0 && t == 0) {
            float* o = out_newxyz + ((size_t)b * NPT + it + 1) * 3;
            o[0] = cx; o[1] = cy; o[2] = cz;
        }
    }

    // keep cluster alive until all in-flight st.async / final reads complete
    asm volatile("barrier.cluster.arrive.aligned;" ::: "memory");
    asm volatile("barrier.cluster.wait.aligned;"   ::: "memory");
}

// =================================================================================
// Kernel 2: feature transpose (B,C,N) -> (B,N,C), tiled 32x32 through smem.
// =================================================================================
__global__ void __launch_bounds__(256)
transpose_kernel(const float* __restrict__ feat)
{
    __shared__ float tile[32][33];
    const int b  = blockIdx.z;
    const int n0 = blockIdx.x * 32;
    const int c0 = blockIdx.y * 32;
    const int tx = threadIdx.x, ty = threadIdx.y;

    const float* src = feat + (size_t)b * NCH * N_PTS;
    #pragma unroll
    for (int i = 0; i < 32; i += 8)
        tile[ty + i][tx] = src[(size_t)(c0 + ty + i) * N_PTS + n0 + tx];
    __syncthreads();

    float* dst = g_featT + (size_t)b * N_PTS * NCH;
    #pragma unroll
    for (int i = 0; i < 32; i += 8)
        dst[(size_t)(n0 + ty + i) * NCH + c0 + tx] = tile[tx][ty + i];
}

// =================================================================================
// Kernel 3: ball query — one warp per centroid, early exit after K found.
// Distance matches the reference's expanded form: d = ((-2*dot) + s2) + n2.
// Qualify iff !(d > r^2); first K in index order; pad with first.
// =================================================================================
__global__ void __launch_bounds__(256)
ball_kernel(const float* __restrict__ xyz, const float* __restrict__ newxyz)
{
    const int wig    = (blockIdx.x * 256 + threadIdx.x) >> 5;   // b*512 + s
    const int lane   = threadIdx.x & 31;
    const int wlocal = threadIdx.x >> 5;
    __shared__ int sid[8][KNB];

    const int b = wig >> 9;
    const float* C = newxyz + (size_t)wig * 3;
    const float cx = C[0], cy = C[1], cz = C[2];
    const float s2 = __fadd_rn(__fadd_rn(__fmul_rn(cx,cx), __fmul_rn(cy,cy)), __fmul_rn(cz,cz));

    const float* X  = xyz  + (size_t)b * N_PTS * 3;
    const float* NN = g_n2 + (size_t)b * N_PTS;

    int cnt = 0;
    for (int basep = 0; basep < N_PTS && cnt < KNB; basep += 32) {
        const int p = basep + lane;
        const float x = X[3*p], y = X[3*p+1], z = X[3*p+2];
        float dot = __fmul_rn(cx, x);
        dot = __fmaf_rn(cy, y, dot);
        dot = __fmaf_rn(cz, z, dot);
        const float d = __fadd_rn(__fadd_rn(__fmul_rn(-2.0f, dot), s2), NN[p]);
        const bool q = !(d > R2);
        const unsigned m = __ballot_sync(0xffffffffu, q);
        const int pos = cnt + __popc(m & ((1u << lane) - 1u));
        if (q && pos < KNB) sid[wlocal][pos] = p;
        cnt += __popc(m);
    }
    __syncwarp();

    const int first = sid[wlocal][0];          // cnt==0 impossible: centroid itself qualifies
    const int v = (lane < cnt) ? sid[wlocal][lane] : first;
    g_idx[(size_t)wig * KNB + lane] = v;
}

// =================================================================================
// Kernel 4: masked max pool from transposed features — block per (b,s), thread=c.
// Warp lanes read consecutive channels -> fully coalesced 128B gathers.
// =================================================================================
__global__ void __launch_bounds__(128)
pool_kernel(float* __restrict__ out)
{
    const int g = blockIdx.x;             // b*512 + s
    const int c = threadIdx.x;
    const int b = g >> 9;
    const int s = g & 511;

    __shared__ int nb[KNB];
    if (c < KNB) nb[c] = g_idx[(size_t)g * KNB + c];
    __syncthreads();

    const float* F = g_featT + (size_t)b * N_PTS * NCH;

    float m0 = F[(size_t)nb[0] * NCH + c];
    float m1 = F[(size_t)nb[1] * NCH + c];
    float m2 = F[(size_t)nb[2] * NCH + c];
    float m3 = F[(size_t)nb[3] * NCH + c];
    #pragma unroll
    for (int k = 4; k < KNB; k += 4) {
        m0 = fmaxf(m0, F[(size_t)nb[k]   * NCH + c]);
        m1 = fmaxf(m1, F[(size_t)nb[k+1] * NCH + c]);
        m2 = fmaxf(m2, F[(size_t)nb[k+2] * NCH + c]);
        m3 = fmaxf(m3, F[(size_t)nb[k+3] * NCH + c]);
    }
    const float m = fmaxf(fmaxf(m0, m1), fmaxf(m2, m3));

    out[(size_t)B_SZ*NPT*3 + ((size_t)b * NCH + c) * NPT + s] = m;
}

// =================================================================================
extern "C" void kernel_launch(void* const* d_in, const int* in_sizes, int n_in,
                              void* d_out, int out_size)
{
    const float* xyz  = (const float*)d_in[0];   // (8, 16384, 3) fp32
    const float* feat = (const float*)d_in[1];   // (8, 128, 16384) fp32
    float* out = (float*)d_out;                  // new_xyz (12288) ++ sub_features (524288)

    dim3 tgrid(N_PTS / 32, NCH / 32, B_SZ);
    dim3 tblk(32, 8);
    transpose_kernel<<<tgrid, tblk>>>(feat);

    dim3 fgrid(CLUSTER, B_SZ);
    fps_kernel<<<fgrid, FPS_THR>>>(xyz, out);

    ball_kernel<<<(B_SZ * NPT * 32) / 256, 256>>>(xyz, out);
    pool_kernel<<<B_SZ * NPT, 128>>>(out);
}